// round 8
// baseline (speedup 1.0000x reference)
#include <cuda_runtime.h>
#include <cuda_fp16.h>
#include <math.h>

#define N_NODES 200000
#define N_PAIRS (N_NODES / 2)              // 100,000
#define N_EDGES 12800000
#define ALPHA   0.1f
#define DT      0.01f
#define EPS_    1e-9f
#define DIFF_   10.0f
#define HARD    1.57079632679489662f

#define EPT      16                        // edges per unit (N_EDGES % 16 == 0)
#define N_UNITS  (N_EDGES / EPT)           // 800,000
#define MAXIT_P  4                         // max pair iterations (grid >= 98 blocks)

// Scratch (device globals — no allocation allowed)
__device__ __half2  g_uv[N_NODES];
__device__ float2   g_sum[N_NODES];
__device__ unsigned g_bar_count = 0;
__device__ unsigned g_bar_gen   = 0;

__device__ __forceinline__ void grid_barrier()
{
    __syncthreads();
    if (threadIdx.x == 0) {
        unsigned g = *(volatile unsigned*)&g_bar_gen;
        __threadfence();
        unsigned arr = atomicAdd(&g_bar_count, 1u);
        if (arr == gridDim.x - 1) {
            g_bar_count = 0;
            __threadfence();
            atomicAdd(&g_bar_gen, 1u);
        } else {
            while (*(volatile unsigned*)&g_bar_gen == g) { }
        }
        __threadfence();
    }
    __syncthreads();
}

__global__ void __launch_bounds__(256, 2) mega_kernel(
    const float* __restrict__ phase,
    const float* __restrict__ xy,
    const float* __restrict__ xy_dot_old,
    const float* __restrict__ w,
    const float* __restrict__ amp,
    const float* __restrict__ ha,
    const int*   __restrict__ src,
    const int*   __restrict__ dst,
    float*       __restrict__ out)
{
    const int T    = gridDim.x * 256;
    const int t    = blockIdx.x * 256 + threadIdx.x;
    const int lane = threadIdx.x & 31;

    // ---------------- Phase A: uv + zero sums; cache (c,s) for Phase C -----
    float4 cs[MAXIT_P];
    #pragma unroll
    for (int it = 0; it < MAXIT_P; it++) {
        int u = t + it * T;
        if (u < N_PAIRS) {
            float2 ph = ((const float2*)phase)[u];
            float4 p  = ((const float4*)xy)[u];      // (x0,y0,x1,y1)
            float s0, c0, s1, c1;
            __sincosf(ph.x, &s0, &c0);
            __sincosf(ph.y, &s1, &c1);
            cs[it] = make_float4(c0, s0, c1, s1);
            __half2 u0 = __floats2half2_rn(fmaf(c0, p.x,  s0 * p.y),
                                           fmaf(c0, p.y, -s0 * p.x));
            __half2 u1 = __floats2half2_rn(fmaf(c1, p.z,  s1 * p.w),
                                           fmaf(c1, p.w, -s1 * p.z));
            ((uint2*)g_uv)[u]  = make_uint2(*(unsigned*)&u0, *(unsigned*)&u1);
            ((float4*)g_sum)[u] = make_float4(0.f, 0.f, 0.f, 0.f);
        }
    }

    grid_barrier();

    // ---------------- Phase B: edges (warp-uniform grid-stride) ------------
    for (int ubase = t - lane; ubase < N_UNITS; ubase += T) {
        int u = ubase + lane;
        bool active = (u < N_UNITS);
        int base = (active ? u : N_UNITS - 1) * EPT;

        int4 s0 = __ldcs((const int4*)(src + base) + 0);
        int4 s1 = __ldcs((const int4*)(src + base) + 1);
        int4 s2 = __ldcs((const int4*)(src + base) + 2);
        int4 s3 = __ldcs((const int4*)(src + base) + 3);
        int4 d0 = __ldcs((const int4*)(dst + base) + 0);
        int4 d1 = __ldcs((const int4*)(dst + base) + 1);
        int4 d2 = __ldcs((const int4*)(dst + base) + 2);
        int4 d3 = __ldcs((const int4*)(dst + base) + 3);

        int k[EPT] = { s0.x, s0.y, s0.z, s0.w,  s1.x, s1.y, s1.z, s1.w,
                       s2.x, s2.y, s2.z, s2.w,  s3.x, s3.y, s3.z, s3.w };
        int di[EPT] = { d0.x, d0.y, d0.z, d0.w,  d1.x, d1.y, d1.z, d1.w,
                        d2.x, d2.y, d2.z, d2.w,  d3.x, d3.y, d3.z, d3.w };

        __half2 h[EPT];
        #pragma unroll
        for (int e = 0; e < EPT; e++) h[e] = __ldg(&g_uv[di[e]]);

        int cur = k[0];
        float2 f0 = __half22float2(h[0]);
        float U = f0.x, V = f0.y;
        #pragma unroll
        for (int e = 1; e < EPT; e++) {
            float2 f = __half22float2(h[e]);
            if (k[e] != cur) {
                if (active) {
                    atomicAdd(&g_sum[cur].x, U);
                    atomicAdd(&g_sum[cur].y, V);
                }
                cur = k[e];
                U = f.x; V = f.y;
            } else {
                U += f.x; V += f.y;
            }
        }

        if (!active) { U = 0.0f; V = 0.0f; cur = -1; }
        #pragma unroll
        for (int o = 1; o < 32; o <<= 1) {
            int   pk = __shfl_up_sync(0xffffffffu, cur, o);
            float pU = __shfl_up_sync(0xffffffffu, U, o);
            float pV = __shfl_up_sync(0xffffffffu, V, o);
            if (lane >= o && pk == cur) { U += pU; V += pV; }
        }
        int nk = __shfl_down_sync(0xffffffffu, cur, 1);
        if (active && (lane == 31 || nk != cur)) {
            atomicAdd(&g_sum[cur].x, U);
            atomicAdd(&g_sum[cur].y, V);
        }
    }

    grid_barrier();

    // ---------------- Phase C: finalize (reuses cached c,s) ----------------
    #pragma unroll
    for (int it = 0; it < MAXIT_P; it++) {
        int u = t + it * T;
        if (u < N_PAIRS) {
            float4 sv = ((const float4*)g_sum)[u];
            float4 p  = ((const float4*)xy)[u];
            float4 pd = ((const float4*)xy_dot_old)[u];
            float2 wi = ((const float2*)w)[u];
            float2 am = ((const float2*)amp)[u];
            float2 hi = ((const float2*)ha)[u];
            float4 C  = cs[it];    // (c0,s0,c1,s1)

            // node 0
            float sx0 = fmaf(C.x, sv.x, -C.y * sv.y);
            float sy0 = fmaf(C.y, sv.x,  C.x * sv.y);
            float r20 = fmaf(p.x, p.x, p.y * p.y);
            float a0  = ALPHA * (1.0f - r20 * r20);
            float z0  = 1.0f - hi.x * ((pd.x + EPS_) / (fabsf(pd.x) + EPS_));
            float b0  = wi.x / (z0 + EPS_);
            float kx0 = fmaf(a0, p.x, -b0 * p.y);
            float ky0 = fmaf(b0, p.x,  a0 * p.y);
            float xd0 = fminf(fmaxf(kx0 + sx0, pd.x - DIFF_), pd.x + DIFF_);
            float yd0 = fminf(fmaxf(ky0 + sy0, pd.y - DIFF_), pd.y + DIFF_);
            float xn0 = fmaf(xd0, DT, p.x);
            float yn0 = fmaf(yd0, DT, p.y);
            float an0 = fminf(fmaxf(am.x * yn0, -HARD), HARD);

            // node 1
            float sx1 = fmaf(C.z, sv.z, -C.w * sv.w);
            float sy1 = fmaf(C.w, sv.z,  C.z * sv.w);
            float r21 = fmaf(p.z, p.z, p.w * p.w);
            float a1  = ALPHA * (1.0f - r21 * r21);
            float z1  = 1.0f - hi.y * ((pd.z + EPS_) / (fabsf(pd.z) + EPS_));
            float b1  = wi.y / (z1 + EPS_);
            float kx1 = fmaf(a1, p.z, -b1 * p.w);
            float ky1 = fmaf(b1, p.z,  a1 * p.w);
            float xd1 = fminf(fmaxf(kx1 + sx1, pd.z - DIFF_), pd.z + DIFF_);
            float yd1 = fminf(fmaxf(ky1 + sy1, pd.w - DIFF_), pd.w + DIFF_);
            float xn1 = fmaf(xd1, DT, p.z);
            float yn1 = fmaf(yd1, DT, p.w);
            float an1 = fminf(fmaxf(am.y * yn1, -HARD), HARD);

            ((float2*)out)[u] = make_float2(an0, an1);                      // angles
            ((float4*)(out + N_NODES))[u]     = make_float4(xn0, yn0, xn1, yn1); // xy_new
            ((float4*)(out + 3 * N_NODES))[u] = p;                          // xy_dot_old_new
        }
    }
}

extern "C" void kernel_launch(void* const* d_in, const int* in_sizes, int n_in,
                              void* d_out, int out_size)
{
    const float* xy         = (const float*)d_in[0];
    const float* xy_dot_old = (const float*)d_in[1];
    const float* phase      = (const float*)d_in[2];
    const float* w          = (const float*)d_in[3];
    const float* amplitudes = (const float*)d_in[4];
    const float* ha         = (const float*)d_in[5];
    const int*   edge_src   = (const int*)d_in[6];
    const int*   edge_dst   = (const int*)d_in[7];
    float* out = (float*)d_out;

    // Co-residency-safe grid: blocks must all be resident for the sw barrier.
    int sms = 148, occ = 2;
    cudaDeviceGetAttribute(&sms, cudaDevAttrMultiProcessorCount, 0);
    cudaOccupancyMaxActiveBlocksPerMultiprocessor(&occ, mega_kernel, 256, 0);
    if (occ < 1) occ = 1;
    if (occ > 2) occ = 2;
    int grid = sms * occ;

    mega_kernel<<<grid, 256>>>(phase, xy, xy_dot_old, w, amplitudes, ha,
                               edge_src, edge_dst, out);
}

// round 9
// speedup vs baseline: 1.1074x; 1.1074x over previous
#include <cuda_runtime.h>
#include <cuda_fp16.h>
#include <math.h>

#define N_NODES 200000
#define N_EDGES 12800000
#define ALPHA   0.1f
#define DT      0.01f
#define EPS_    1e-9f
#define DIFF_   10.0f
#define HARD    1.57079632679489662f

#define EPT        16                      // edges per thread
#define N_THREADS  (N_EDGES / EPT)         // 800,000 = 3125 * 256 exactly

// Scratch (device globals — no allocation allowed)
__device__ __half2 g_uv[N_NODES];   // pre-rotated (u,v) = e^{-i phi}(x+iy)
__device__ float2  g_sum[N_NODES];  // per-node gathered sum, atomic-accumulated

__device__ __forceinline__ void pdl_wait()    { asm volatile("griddepcontrol.wait;" ::: "memory"); }
__device__ __forceinline__ void pdl_trigger() { asm volatile("griddepcontrol.launch_dependents;" ::: "memory"); }

// ---------------------------------------------------------------------------
// K1: per-node prep. Trigger FIRST so the edge grid launches concurrently and
// overlaps its streaming prologue with this kernel's sincos work.
// ---------------------------------------------------------------------------
__global__ void __launch_bounds__(256) uv_kernel(
    const float* __restrict__ phase,
    const float* __restrict__ xy)
{
    pdl_trigger();
    int i = blockIdx.x * blockDim.x + threadIdx.x;
    if (i < N_NODES) {
        float s, c;
        __sincosf(phase[i], &s, &c);
        float2 p = ((const float2*)xy)[i];
        g_uv[i]  = __floats2half2_rn(fmaf(c, p.x, s * p.y), fmaf(c, p.y, -s * p.x));
        g_sum[i] = make_float2(0.0f, 0.0f);
    }
}

// ---------------------------------------------------------------------------
// K2: fused edge pass. 16 edges/thread: coalesced int4 streams (issued before
// the PDL wait -> overlap with uv), 16-deep gather MLP, register run-length
// scan, warp shfl segmented merge of pending runs, atomicAdd per run.
// Trigger FIRST so finalize launches early and prefetches its inputs.
// ---------------------------------------------------------------------------
__global__ void __launch_bounds__(256) edge_kernel(
    const int* __restrict__ src,
    const int* __restrict__ dst)
{
    pdl_trigger();
    int t = blockIdx.x * blockDim.x + threadIdx.x;   // grid is exactly N_THREADS
    int lane = threadIdx.x & 31;
    int base = t * EPT;

    // Independent streaming loads (overlap with uv kernel via PDL)
    int4 s0 = __ldcs((const int4*)(src + base) + 0);
    int4 s1 = __ldcs((const int4*)(src + base) + 1);
    int4 s2 = __ldcs((const int4*)(src + base) + 2);
    int4 s3 = __ldcs((const int4*)(src + base) + 3);
    int4 d0 = __ldcs((const int4*)(dst + base) + 0);
    int4 d1 = __ldcs((const int4*)(dst + base) + 1);
    int4 d2 = __ldcs((const int4*)(dst + base) + 2);
    int4 d3 = __ldcs((const int4*)(dst + base) + 3);

    pdl_wait();   // g_uv / g_sum now visible

    int k[EPT] = { s0.x, s0.y, s0.z, s0.w,  s1.x, s1.y, s1.z, s1.w,
                   s2.x, s2.y, s2.z, s2.w,  s3.x, s3.y, s3.z, s3.w };
    int di[EPT] = { d0.x, d0.y, d0.z, d0.w,  d1.x, d1.y, d1.z, d1.w,
                    d2.x, d2.y, d2.z, d2.w,  d3.x, d3.y, d3.z, d3.w };

    __half2 h[EPT];
    #pragma unroll
    for (int e = 0; e < EPT; e++) h[e] = __ldg(&g_uv[di[e]]);

    // Run-length scan over sorted keys; interior runs flush immediately
    int   cur = k[0];
    float2 f0 = __half22float2(h[0]);
    float U = f0.x, V = f0.y;
    #pragma unroll
    for (int e = 1; e < EPT; e++) {
        float2 f = __half22float2(h[e]);
        if (k[e] != cur) {
            atomicAdd(&g_sum[cur].x, U);
            atomicAdd(&g_sum[cur].y, V);
            cur = k[e];
            U = f.x; V = f.y;
        } else {
            U += f.x; V += f.y;
        }
    }

    // Warp segmented merge of pending runs (keys nondecreasing across lanes)
    #pragma unroll
    for (int o = 1; o < 32; o <<= 1) {
        int   pk = __shfl_up_sync(0xffffffffu, cur, o);
        float pU = __shfl_up_sync(0xffffffffu, U, o);
        float pV = __shfl_up_sync(0xffffffffu, V, o);
        if (lane >= o && pk == cur) { U += pU; V += pV; }
    }
    int nk = __shfl_down_sync(0xffffffffu, cur, 1);
    if (lane == 31 || nk != cur) {
        atomicAdd(&g_sum[cur].x, U);
        atomicAdd(&g_sum[cur].y, V);
    }
}

// ---------------------------------------------------------------------------
// K3: thread-per-node finalize. All g_sum-independent loads issued before the
// PDL wait (they overlap the edge kernel's tail).
// ---------------------------------------------------------------------------
__global__ void __launch_bounds__(256) finalize_kernel(
    const float* __restrict__ phase,
    const float* __restrict__ xy,
    const float* __restrict__ xy_dot_old,
    const float* __restrict__ w,
    const float* __restrict__ amp,
    const float* __restrict__ ha,
    float*       __restrict__ out)
{
    int i = blockIdx.x * blockDim.x + threadIdx.x;
    if (i >= N_NODES) { pdl_wait(); return; }

    float  ph = phase[i];
    float2 p  = ((const float2*)xy)[i];
    float2 pd = ((const float2*)xy_dot_old)[i];
    float  wi = w[i];
    float  am = amp[i];
    float  hi = ha[i];

    pdl_wait();   // edge atomics visible
    float2 sv = g_sum[i];

    float s, c;
    __sincosf(ph, &s, &c);
    float sum_x = fmaf(c, sv.x, -s * sv.y);
    float sum_y = fmaf(s, sv.x,  c * sv.y);

    float r2   = fmaf(p.x, p.x, p.y * p.y);
    float a    = ALPHA * (1.0f - r2 * r2);
    float zeta = 1.0f - hi * ((pd.x + EPS_) / (fabsf(pd.x) + EPS_));
    float b    = wi / (zeta + EPS_);

    float kx = fmaf(a, p.x, -b * p.y);
    float ky = fmaf(b, p.x,  a * p.y);

    float x_dot = fminf(fmaxf(kx + sum_x, pd.x - DIFF_), pd.x + DIFF_);
    float y_dot = fminf(fmaxf(ky + sum_y, pd.y - DIFF_), pd.y + DIFF_);

    float xn = fmaf(x_dot, DT, p.x);
    float yn = fmaf(y_dot, DT, p.y);
    float ang = fminf(fmaxf(am * yn, -HARD), HARD);

    out[i] = ang;                                              // angles
    ((float2*)(out + N_NODES))[i]     = make_float2(xn, yn);   // xy_new
    ((float2*)(out + 3 * N_NODES))[i] = p;                     // xy_dot_old_new = xy
}

extern "C" void kernel_launch(void* const* d_in, const int* in_sizes, int n_in,
                              void* d_out, int out_size)
{
    const float* xy         = (const float*)d_in[0];
    const float* xy_dot_old = (const float*)d_in[1];
    const float* phase      = (const float*)d_in[2];
    const float* w          = (const float*)d_in[3];
    const float* amplitudes = (const float*)d_in[4];
    const float* ha         = (const float*)d_in[5];
    const int*   edge_src   = (const int*)d_in[6];
    const int*   edge_dst   = (const int*)d_in[7];
    float* out = (float*)d_out;

    int nb_nodes = (N_NODES + 255) / 256;
    int nb_edge  = N_THREADS / 256;          // 3125, exact

    cudaLaunchAttribute pdl_attr[1];
    pdl_attr[0].id = cudaLaunchAttributeProgrammaticStreamSerialization;
    pdl_attr[0].val.programmaticStreamSerializationAllowed = 1;

    uv_kernel<<<nb_nodes, 256>>>(phase, xy);

    {
        cudaLaunchConfig_t cfg = {};
        cfg.gridDim  = dim3(nb_edge);
        cfg.blockDim = dim3(256);
        cfg.stream   = 0;
        cfg.attrs    = pdl_attr;
        cfg.numAttrs = 1;
        cudaLaunchKernelEx(&cfg, edge_kernel, edge_src, edge_dst);
    }
    {
        cudaLaunchConfig_t cfg = {};
        cfg.gridDim  = dim3(nb_nodes);
        cfg.blockDim = dim3(256);
        cfg.stream   = 0;
        cfg.attrs    = pdl_attr;
        cfg.numAttrs = 1;
        cudaLaunchKernelEx(&cfg, finalize_kernel, phase, xy, xy_dot_old, w,
                           amplitudes, ha, out);
    }
}